// round 13
// baseline (speedup 1.0000x reference)
#include <cuda_runtime.h>
#include <cstdint>

// LFR: M=7, N=6, LEFT=3, D=80 floats = 20 float4/frame, 140 float4/output row.
#define MM 7
#define NN 6
#define LEFTP 3
#define DD 80
#define F4F 20     /* float4 per frame */
#define F4R 140    /* float4 per output row */
#define RPB 8      /* rows per block */
#define SLOTS (NN * RPB + 1)        /* 49 unique frame slots per block */
#define FILL_F4 (SLOTS * F4F)       /* 980 float4 staged in SMEM */
#define OUT_F4 (RPB * F4R)          /* 1120 float4 written per block */
#define TPB 224    /* 7 warps; 1120/224 = 5 outputs per thread */
#define EPT 5

__device__ __forceinline__ int t_all_of(int L) {
    int c6    = (L + 5) / 6;          // ceil(L/6)
    int delta = L + 9 - 6 * c6;       // prepad - N*(n_lfr-1)
    int rp    = 7 - delta; if (rp < 0) rp = 0;
    return 3 + L + rp;
}

// x (84MB < 126MB L2) is re-read identically every replay: evict_last policy
// keeps it resident across replays (R8: -1.5us).
__device__ __forceinline__ uint64_t make_evict_last_policy() {
    uint64_t pol;
    asm("createpolicy.fractional.L2::evict_last.b64 %0, 1.0;" : "=l"(pol));
    return pol;
}
// 16B L2->SMEM async copy (bypasses L1/registers), with residency hint.
__device__ __forceinline__ void cp16_el(uint32_t smem_addr, const float4* g, uint64_t pol) {
    asm volatile("cp.async.cg.shared.global.L2::cache_hint [%0], [%1], 16, %2;"
                 :: "r"(smem_addr), "l"(g), "l"(pol));
}

// grid = (ceil(nf/RPB), B), block = TPB.
// Stage: SMEM slot q (q=0..6*RPB) holds x frame src(6*f0+q), where
//   src(t) = (t < L+3) ? max(t-3, 0) : fb      (clamping done ONCE at fill)
// Expand: out element e (=140*f_loc+r) of row f0+f_loc reads SMEM f4 (e - 20*f_loc),
// since frames of row f_loc start at slot 6*f_loc.
__global__ __launch_bounds__(TPB)
void lfr_fused_kernel(const float4* __restrict__ x4,
                      float4* __restrict__ out4,
                      const int* __restrict__ lens,
                      float* __restrict__ newlen,
                      int T, int nf, int B, int write_newlen) {
    __shared__ float4 s_tile[FILL_F4];
    __shared__ int    s_max[TPB / 32];

    const int b   = blockIdx.y;
    const int f0  = blockIdx.x * RPB;
    const int tid = threadIdx.x;

    const int L     = __ldg(&lens[b]);
    const int limit = L + LEFTP;

    // Per-batch new_len written once, by block (0, b).
    if (write_newlen && blockIdx.x == 0 && tid == 0)
        newlen[b] = (float)(t_all_of(L) / NN);

    // fb needed iff some staged slot has t = 6*f0+q >= limit.
    const bool need_fb = (NN * f0 + NN * RPB) >= limit;   // block-uniform
    int fb = 0;
    if (need_fb) {
        // Tmax = max over batch of T_all (lens[] is tiny and L2-hot).
        int v = 0;
        if (tid < B) v = t_all_of(__ldg(&lens[tid]));
        #pragma unroll
        for (int off = 16; off; off >>= 1)
            v = max(v, __shfl_xor_sync(0xffffffffu, v, off));
        if ((tid & 31) == 0) s_max[tid >> 5] = v;
        __syncthreads();
        int Tmax = s_max[0];
        #pragma unroll
        for (int w = 1; w < TPB / 32; w++) Tmax = max(Tmax, s_max[w]);
        const int jmax = Tmax - 1;                     // padded index for masked slots
        fb = (jmax < LEFTP + T) ? (jmax - LEFTP) : (L - 1);
    }

    const uint64_t pol = make_evict_last_policy();
    const size_t xb = (size_t)b * T * F4F;                 // x4 base for batch
    const size_t ob = ((size_t)b * nf + f0) * F4R;         // out4 base (row f0)

    // ── Fill: stage 49 unique (clamped) frames, each x float4 loaded once ──
    const uint32_t s_base = (uint32_t)__cvta_generic_to_shared(s_tile);
    #pragma unroll
    for (int i = tid; i < FILL_F4; i += TPB) {
        const int q   = (i * 205) >> 12;                   // exact i/20 for i<1024
        const int c   = i - q * F4F;
        const int t   = NN * f0 + q;
        const int tm3 = t - LEFTP;
        const int src = (t < limit) ? (tm3 < 0 ? 0 : tm3) : fb;
        cp16_el(s_base + i * 16u, &x4[xb + src * F4F + c], pol);
    }
    asm volatile("cp.async.commit_group;");
    asm volatile("cp.async.wait_group 0;");
    __syncthreads();

    // ── Expand: 5 coalesced stores per thread from SMEM ──
    #pragma unroll
    for (int s = 0; s < EPT; s++) {
        const int e     = tid + s * TPB;                   // 0..1119
        const int f_loc = (e * 937) >> 17;                 // exact e/140 for e<1213
        if (f0 + f_loc >= nf) continue;
        const float4 v = s_tile[e - f_loc * F4F];          // slot-relative read
        __stcs(&out4[ob + e], v);                          // evict-first store
    }
}

extern "C" void kernel_launch(void* const* d_in, const int* in_sizes, int n_in,
                              void* d_out, int out_size) {
    const float* x    = (const float*)d_in[0];
    const int*   lens = (const int*)d_in[1];

    int B = in_sizes[1];                 // 64
    int T = in_sizes[0] / (B * DD);      // 4096

    long long per = (long long)B * (MM * DD);   // output elems per frame-row across batch
    long long nf;
    int write_newlen = 0;
    if (out_size > B && ((long long)(out_size - B) % per) == 0) {
        write_newlen = 1;
        nf = ((long long)out_size - B) / per;
    } else {
        nf = (long long)out_size / per;
    }

    float* out    = (float*)d_out;
    float* newlen = out + (long long)B * nf * (MM * DD);

    dim3 grid(((int)nf + RPB - 1) / RPB, B);
    lfr_fused_kernel<<<grid, TPB>>>((const float4*)x, (float4*)out,
                                    lens, newlen, T, (int)nf, B, write_newlen);
}

// round 14
// speedup vs baseline: 1.5444x; 1.5444x over previous
#include <cuda_runtime.h>
#include <cstdint>

// LFR: M=7, N=6, LEFT=3, D=80 floats = 20 float4 per frame, 140 float4 per output row.
#define MM 7
#define NN 6
#define LEFTP 3
#define DD 80
#define F4F 20     /* float4 per frame */
#define F4R 140    /* float4 per row (7 frames) */
#define RPB 16     /* rows per block -> 2240 float4 per block */
#define TPB 320    /* 10 warps; 2240/320 = 7 elements per thread, all threads active */
#define EPT 7      /* elements per thread (MLP_p1 = 7) */

__device__ __forceinline__ int t_all_of(int L) {
    int c6    = (L + 5) / 6;          // ceil(L/6)
    int delta = L + 9 - 6 * c6;       // prepad - N*(n_lfr-1)
    int rp    = 7 - delta; if (rp < 0) rp = 0;
    return 3 + L + rp;
}

// x is 84MB (< 126MB L2) and re-read identically every graph replay: keep it
// L2-resident across replays with an evict_last cache policy (R8: -1.5us).
__device__ __forceinline__ uint64_t make_evict_last_policy() {
    uint64_t pol;
    asm("createpolicy.fractional.L2::evict_last.b64 %0, 1.0;" : "=l"(pol));
    return pol;
}
__device__ __forceinline__ float4 ldg_evict_last(const float4* p, uint64_t pol) {
    float4 v;
    asm volatile("ld.global.nc.L2::cache_hint.v4.f32 {%0,%1,%2,%3}, [%4], %5;"
                 : "=f"(v.x), "=f"(v.y), "=f"(v.z), "=f"(v.w)
                 : "l"(p), "l"(pol));
    return v;
}

// grid = (ceil(nf/RPB), B), block = TPB.
// Block covers output float4s e in [0, 2240) of rows [f0, f0+16); thread owns
// e = tid + s*320, s = 0..6. Decode: f_loc = e/140, r = e%140 (exact magic).
// out[b, f, r] = x4[b, src_f4]:
//   interior row:  src_f4 = (6f-3)*20 + r          (contiguous slice)
//   boundary row:  m = r/20; t = 6f+m; src = t<L+3 ? max(t-3,0) : fb
__global__ __launch_bounds__(TPB)
void lfr_fused_kernel(const float4* __restrict__ x4,
                      float4* __restrict__ out4,
                      const int* __restrict__ lens,
                      float* __restrict__ newlen,
                      int T, int nf, int B, int write_newlen) {
    const int b   = blockIdx.y;
    const int f0  = blockIdx.x * RPB;
    const int tid = threadIdx.x;

    const int L     = __ldg(&lens[b]);
    const int limit = L + LEFTP;

    // Per-batch new_len written once, by block (0, b).
    if (write_newlen && blockIdx.x == 0 && tid == 0)
        newlen[b] = (float)(t_all_of(L) / NN);

    // Does this block contain any row touching t >= limit (needs fb)?
    const int fLast    = min(f0 + RPB - 1, nf - 1);
    const bool need_fb = (NN * fLast + NN) >= limit;   // block-uniform

    __shared__ int s_max[TPB / 32];
    int fb = 0;
    if (need_fb) {
        // Tmax = max over batch of T_all (lens[] is tiny and L2-hot).
        int v = 0;
        if (tid < B) v = t_all_of(__ldg(&lens[tid]));
        #pragma unroll
        for (int off = 16; off; off >>= 1)
            v = max(v, __shfl_xor_sync(0xffffffffu, v, off));
        if ((tid & 31) == 0) s_max[tid >> 5] = v;
        __syncthreads();
        int Tmax = s_max[0];
        #pragma unroll
        for (int w = 1; w < TPB / 32; w++) Tmax = max(Tmax, s_max[w]);
        const int jmax = Tmax - 1;                     // padded index for masked slots
        fb = (jmax < LEFTP + T) ? (jmax - LEFTP) : (L - 1);
    }

    const uint64_t pol = make_evict_last_policy();

    const size_t xb = (size_t)b * T * F4F;                 // x4 base for batch
    const size_t ob = ((size_t)b * nf + f0) * F4R;         // out4 base (row f0)

    float4 v[EPT];
    bool   ok[EPT];

    #pragma unroll
    for (int s = 0; s < EPT; s++) {
        const int e     = tid + s * TPB;                   // 0..2239
        const int f_loc = (e * 7490) >> 20;                // exact e/140 for e<2240
        const int r     = e - f_loc * F4R;                 // e%140
        const int f     = f0 + f_loc;
        ok[s] = (f < nf);
        if (!ok[s]) continue;
        int src_f4;
        if (f >= 1 && (NN * f + NN) < limit) {
            // Interior row: contiguous slice of x, no per-frame decode needed.
            src_f4 = (NN * f - LEFTP) * F4F + r;
        } else {
            // Boundary row: per-element clamp / fallback.
            const int m   = (r * 205) >> 12;               // exact r/20 for r<140
            const int t   = NN * f + m;
            const int tm3 = t - LEFTP;
            const int src = (t < limit) ? (tm3 < 0 ? 0 : tm3) : fb;
            src_f4 = src * F4F + (r - m * F4F);
        }
        v[s] = ldg_evict_last(&x4[xb + src_f4], pol);
    }

    #pragma unroll
    for (int s = 0; s < EPT; s++)
        if (ok[s]) __stcs(&out4[ob + tid + s * TPB], v[s]);   // evict-first store
}

extern "C" void kernel_launch(void* const* d_in, const int* in_sizes, int n_in,
                              void* d_out, int out_size) {
    const float* x    = (const float*)d_in[0];
    const int*   lens = (const int*)d_in[1];

    int B = in_sizes[1];                 // 64
    int T = in_sizes[0] / (B * DD);      // 4096

    long long per = (long long)B * (MM * DD);   // output elems per frame-row across batch
    long long nf;
    int write_newlen = 0;
    if (out_size > B && ((long long)(out_size - B) % per) == 0) {
        write_newlen = 1;
        nf = ((long long)out_size - B) / per;
    } else {
        nf = (long long)out_size / per;
    }

    float* out    = (float*)d_out;
    float* newlen = out + (long long)B * nf * (MM * DD);

    dim3 grid(((int)nf + RPB - 1) / RPB, B);
    lfr_fused_kernel<<<grid, TPB>>>((const float4*)x, (float4*)out,
                                    lens, newlen, T, (int)nf, B, write_newlen);
}